// round 1
// baseline (speedup 1.0000x reference)
#include <cuda_runtime.h>

// ---------------------------------------------------------------------------
// Problem constants
//   x: (8, 16, 4, 64, 64) f32      A_IN=16, C_IN=4
//   W: (256, 16, 5, 5)    f32      C_OUT*A_OUT=256
//   b: (1, 1, 8, 32)      f32
//   out: (8, 32, 8, 64, 64) f32
// ---------------------------------------------------------------------------

// Scratch (static device globals; allocation-free rule)
static __device__ float g_t[32 * 16 * 64 * 64];       // conv input, "t" reinterpretation (8 MB)
static __device__ float g_wt[16 * 25 * 256];          // weights transposed to [ic][k][o]
static __device__ float g_conv[32 * 256 * 64 * 64];   // conv output == votes (134 MB)

// ---------------------------------------------------------------------------
// prep_t: build t buffer.
// t_flat[j], j = (((ci*8+b)*64+h)*64+w)*16 + a   equals x[b,a,ci,h,w].
// Conv later reads t as NCHW (32, 16, 64, 64) from this same flat buffer.
// ---------------------------------------------------------------------------
__global__ void prep_t_kernel(const float* __restrict__ x) {
    int j = blockIdx.x * 256 + threadIdx.x;   // 0 .. 2097151
    int a  = j & 15;
    int w  = (j >> 4) & 63;
    int h  = (j >> 10) & 63;
    int nb = j >> 16;            // ci*8 + b
    int ci = nb >> 3;
    int b  = nb & 7;
    g_t[j] = x[(((b * 16 + a) * 4 + ci) << 12) + (h << 6) + w];
}

// ---------------------------------------------------------------------------
// prep_w: transpose W (o, ic, kh, kw) -> wt[(ic*25+k)*256 + o] so the conv
// kernel's smem fills are coalesced.
// ---------------------------------------------------------------------------
__global__ void prep_w_kernel(const float* __restrict__ W) {
    int m = blockIdx.x * 256 + threadIdx.x;   // 0 .. 102399
    int o = m & 255;
    int r = m >> 8;          // 0..399
    int k = r % 25;
    int ic = r / 25;
    g_wt[m] = W[o * 400 + ic * 25 + k];
}

// ---------------------------------------------------------------------------
// conv: out[n,o,y,x] = sum_{c,kh,kw} t[n,c,y+kh-2,x+kw-2] * W[o,c,kh,kw]
// block tile: fixed n, 128 o, 8h x 16w pixels. 256 threads.
// thread: og = tid/16 (8 o's = og*8..), pg = tid%16 -> hl = pg>>1, wl = (pg&1)*8
// per-thread 8o x 8px accumulators.
// ---------------------------------------------------------------------------
__global__ __launch_bounds__(256, 2) void conv_kernel() {
    const int tile  = blockIdx.x;          // 0..31  (4 w-tiles x 8 h-tiles)
    const int wbase = (tile & 3) * 16;
    const int hbase = (tile >> 2) * 8;
    const int obase = blockIdx.y * 128;    // 0 or 128
    const int n     = blockIdx.z;          // 0..31
    const int tid   = threadIdx.x;
    const int og    = tid >> 4;            // 0..15
    const int pg    = tid & 15;
    const int hl    = pg >> 1;             // 0..7
    const int wl    = (pg & 1) * 8;        // 0 or 8

    __shared__ __align__(16) float s_in[12 * 20];     // padded input patch (one ic)
    __shared__ __align__(16) float s_w[25 * 128];     // weights [k][o_local] (one ic)

    float acc[8][8];
#pragma unroll
    for (int o = 0; o < 8; o++)
#pragma unroll
        for (int j = 0; j < 8; j++) acc[o][j] = 0.f;

    const float* tn = g_t + n * 65536;

    for (int ic = 0; ic < 16; ic++) {
        __syncthreads();
        // input patch: rows hbase-2..hbase+9, cols wbase-2..wbase+17 (zero pad)
        if (tid < 240) {
            int r = tid / 20, c = tid % 20;
            int gy = hbase + r - 2;
            int gx = wbase + c - 2;
            float v = 0.f;
            if ((unsigned)gy < 64u && (unsigned)gx < 64u)
                v = tn[ic * 4096 + gy * 64 + gx];
            s_in[r * 20 + c] = v;
        }
        // weights: 25 x 128, coalesced from g_wt
        const float* wsrc = g_wt + ic * 25 * 256 + obase;
#pragma unroll
        for (int idx = tid; idx < 3200; idx += 256) {
            int k  = idx >> 7;
            int ol = idx & 127;
            s_w[idx] = wsrc[k * 256 + ol];
        }
        __syncthreads();

#pragma unroll
        for (int kh = 0; kh < 5; kh++) {
            float rin[12];
            const float4* rowp =
                (const float4*)&s_in[(hl + kh) * 20 + wl];
            float4 r0 = rowp[0], r1 = rowp[1], r2 = rowp[2];
            rin[0] = r0.x; rin[1] = r0.y; rin[2]  = r0.z; rin[3]  = r0.w;
            rin[4] = r1.x; rin[5] = r1.y; rin[6]  = r1.z; rin[7]  = r1.w;
            rin[8] = r2.x; rin[9] = r2.y; rin[10] = r2.z; rin[11] = r2.w;
#pragma unroll
            for (int kw = 0; kw < 5; kw++) {
                const float4* wp =
                    (const float4*)&s_w[(kh * 5 + kw) * 128 + og * 8];
                float4 w0 = wp[0], w1 = wp[1];
                float wreg[8] = {w0.x, w0.y, w0.z, w0.w, w1.x, w1.y, w1.z, w1.w};
#pragma unroll
                for (int o = 0; o < 8; o++)
#pragma unroll
                    for (int j = 0; j < 8; j++)
                        acc[o][j] = fmaf(wreg[o], rin[kw + j], acc[o][j]);
            }
        }
    }

    // write conv output: flat = n*1048576 + o*4096 + y*64 + x
    float* outp = g_conv + n * 1048576 + (obase + og * 8) * 4096
                + (hbase + hl) * 64 + wbase + wl;
#pragma unroll
    for (int o = 0; o < 8; o++) {
        float4 v0 = {acc[o][0], acc[o][1], acc[o][2], acc[o][3]};
        float4 v1 = {acc[o][4], acc[o][5], acc[o][6], acc[o][7]};
        *(float4*)(outp + o * 4096)     = v0;
        *(float4*)(outp + o * 4096 + 4) = v1;
    }
}

// ---------------------------------------------------------------------------
// routing: one warp per pixel (b,h,w). lane = a (32 atoms).
// votes[b,i,h,w,o,a] = g_conv_flat[b*4194304 + i*1048576 + hw*256 + o*32 + a]
// 3 routing iterations fused in registers; skip dead final agreement.
// out[b,a,o,h,w] = activation.
// ---------------------------------------------------------------------------
__global__ __launch_bounds__(256) void routing_kernel(const float* __restrict__ bias,
                                                      float* __restrict__ out) {
    const unsigned FULL = 0xffffffffu;
    int gwarp = (blockIdx.x * 256 + threadIdx.x) >> 5;   // 0..32767
    int lane  = threadIdx.x & 31;
    int b  = gwarp >> 12;
    int hw = gwarp & 4095;

    const float* vb = g_conv + b * 4194304 + hw * 256 + lane;
    float v[4][8];
#pragma unroll
    for (int i = 0; i < 4; i++)
#pragma unroll
        for (int o = 0; o < 8; o++)
            v[i][o] = vb[i * 1048576 + o * 32];

    float bia[8];
#pragma unroll
    for (int o = 0; o < 8; o++) bia[o] = bias[o * 32 + lane];

    // lane l holds logits[i = l>>3][o = l&7]
    float logit = 0.f;
    float act[8];

#pragma unroll
    for (int it = 0; it < 3; it++) {
        // softmax over o within 8-lane groups
        float m = logit;
        m = fmaxf(m, __shfl_xor_sync(FULL, m, 1));
        m = fmaxf(m, __shfl_xor_sync(FULL, m, 2));
        m = fmaxf(m, __shfl_xor_sync(FULL, m, 4));
        float e = __expf(logit - m);
        float s = e;
        s += __shfl_xor_sync(FULL, s, 1);
        s += __shfl_xor_sync(FULL, s, 2);
        s += __shfl_xor_sync(FULL, s, 4);
        float route = e / s;

        float pre[8];
#pragma unroll
        for (int o = 0; o < 8; o++) {
            float p = bia[o];
#pragma unroll
            for (int i = 0; i < 4; i++) {
                float r = __shfl_sync(FULL, route, i * 8 + o);
                p = fmaf(r, v[i][o], p);
            }
            pre[o] = p;
        }

        // squash per o: full 32-lane reduction of pre^2
#pragma unroll
        for (int o = 0; o < 8; o++) {
            float sq = pre[o] * pre[o];
            sq += __shfl_xor_sync(FULL, sq, 1);
            sq += __shfl_xor_sync(FULL, sq, 2);
            sq += __shfl_xor_sync(FULL, sq, 4);
            sq += __shfl_xor_sync(FULL, sq, 8);
            sq += __shfl_xor_sync(FULL, sq, 16);
            float f = sq / ((1.f + sq) * sqrtf(sq + 1e-7f));
            act[o] = pre[o] * f;
        }

        if (it < 2) {
#pragma unroll
            for (int i = 0; i < 4; i++) {
#pragma unroll
                for (int o = 0; o < 8; o++) {
                    float g = v[i][o] * act[o];
                    g += __shfl_xor_sync(FULL, g, 1);
                    g += __shfl_xor_sync(FULL, g, 2);
                    g += __shfl_xor_sync(FULL, g, 4);
                    g += __shfl_xor_sync(FULL, g, 8);
                    g += __shfl_xor_sync(FULL, g, 16);
                    logit += (lane == (i * 8 + o)) ? g : 0.f;
                }
            }
        }
    }

    // out (B, A=32, C=8, h, w): flat = ((b*32 + a)*8 + o)*4096 + hw
    float* ob = out + ((b * 32 + lane) * 8) * 4096 + hw;
#pragma unroll
    for (int o = 0; o < 8; o++)
        ob[o * 4096] = act[o];
}

// ---------------------------------------------------------------------------
extern "C" void kernel_launch(void* const* d_in, const int* in_sizes, int n_in,
                              void* d_out, int out_size) {
    const float* x = (const float*)d_in[0];   // 2,097,152
    const float* W = (const float*)d_in[1];   //   102,400
    const float* b = (const float*)d_in[2];   //       256
    float* out = (float*)d_out;               // 8,388,608

    prep_t_kernel<<<8192, 256>>>(x);
    prep_w_kernel<<<400, 256>>>(W);
    conv_kernel<<<dim3(32, 2, 32), 256>>>();
    routing_kernel<<<4096, 256>>>(b, out);
}

// round 2
// speedup vs baseline: 1.1028x; 1.1028x over previous
#include <cuda_runtime.h>

// ---------------------------------------------------------------------------
// Problem constants
//   x: (8, 16, 4, 64, 64) f32      A_IN=16, C_IN=4
//   W: (256, 16, 5, 5)    f32      C_OUT*A_OUT=256
//   b: (1, 1, 8, 32)      f32
//   out: (8, 32, 8, 64, 64) f32
// ---------------------------------------------------------------------------

static __device__ float g_t[32 * 16 * 64 * 64];       // conv input "t" (8 MB)
static __device__ float g_wt[16 * 25 * 256];          // weights [ic][k][o]
static __device__ float g_conv[32 * 256 * 64 * 64];   // conv output == votes (134 MB)

// ---- packed f32x2 helpers --------------------------------------------------
__device__ __forceinline__ unsigned long long pk2(float lo, float hi) {
    unsigned long long d;
    asm("mov.b64 %0, {%1,%2};" : "=l"(d) : "f"(lo), "f"(hi));
    return d;
}
__device__ __forceinline__ unsigned long long ffma2(unsigned long long a,
                                                    unsigned long long b,
                                                    unsigned long long c) {
    unsigned long long d;
    asm("fma.rn.f32x2 %0, %1, %2, %3;" : "=l"(d) : "l"(a), "l"(b), "l"(c));
    return d;
}
__device__ __forceinline__ void upk2(unsigned long long d, float& lo, float& hi) {
    asm("mov.b64 {%0,%1}, %2;" : "=f"(lo), "=f"(hi) : "l"(d));
}

// ---------------------------------------------------------------------------
// prep_t: t_flat[j], j = (((ci*8+b)*64+h)*64+w)*16 + a  ==  x[b,a,ci,h,w]
// ---------------------------------------------------------------------------
__global__ void prep_t_kernel(const float* __restrict__ x) {
    int j = blockIdx.x * 256 + threadIdx.x;
    int a  = j & 15;
    int w  = (j >> 4) & 63;
    int h  = (j >> 10) & 63;
    int nb = j >> 16;
    int ci = nb >> 3;
    int b  = nb & 7;
    g_t[j] = x[(((b * 16 + a) * 4 + ci) << 12) + (h << 6) + w];
}

__global__ void prep_w_kernel(const float* __restrict__ W) {
    int m = blockIdx.x * 256 + threadIdx.x;
    int o = m & 255;
    int r = m >> 8;
    int k = r % 25;
    int ic = r / 25;
    g_wt[m] = W[o * 400 + ic * 25 + k];
}

// ---------------------------------------------------------------------------
// conv with packed FFMA2: accumulators pair adjacent output channels.
// block: fixed n, 128 o, 8h x 16w. 256 threads; thread: 8 o x 8 px.
// ---------------------------------------------------------------------------
__global__ __launch_bounds__(256, 2) void conv_kernel() {
    const int tile  = blockIdx.x;          // 0..31
    const int wbase = (tile & 3) * 16;
    const int hbase = (tile >> 2) * 8;
    const int obase = blockIdx.y * 128;
    const int n     = blockIdx.z;
    const int tid   = threadIdx.x;
    const int og    = tid >> 4;            // 0..15
    const int pg    = tid & 15;
    const int hl    = pg >> 1;
    const int wl    = (pg & 1) * 8;

    __shared__ __align__(16) float s_in[12 * 20];
    __shared__ __align__(16) float s_w[25 * 128];

    // acc2[p][j]: lo half = channel og*8+2p, hi half = og*8+2p+1, pixel j
    unsigned long long acc2[4][8];
#pragma unroll
    for (int p = 0; p < 4; p++)
#pragma unroll
        for (int j = 0; j < 8; j++) acc2[p][j] = 0ull;

    const float* tn = g_t + n * 65536;

    for (int ic = 0; ic < 16; ic++) {
        __syncthreads();
        if (tid < 240) {
            int r = tid / 20, c = tid % 20;
            int gy = hbase + r - 2;
            int gx = wbase + c - 2;
            float v = 0.f;
            if ((unsigned)gy < 64u && (unsigned)gx < 64u)
                v = tn[ic * 4096 + gy * 64 + gx];
            s_in[r * 20 + c] = v;
        }
        const float* wsrc = g_wt + ic * 25 * 256 + obase;
#pragma unroll
        for (int idx = tid; idx < 3200; idx += 256) {
            int k  = idx >> 7;
            int ol = idx & 127;
            s_w[idx] = wsrc[k * 256 + ol];
        }
        __syncthreads();

#pragma unroll
        for (int kh = 0; kh < 5; kh++) {
            const float4* rowp = (const float4*)&s_in[(hl + kh) * 20 + wl];
            float4 r0 = rowp[0], r1 = rowp[1], r2 = rowp[2];
            float rin[12] = {r0.x, r0.y, r0.z, r0.w, r1.x, r1.y, r1.z, r1.w,
                             r2.x, r2.y, r2.z, r2.w};
            // broadcast pairs (r, r), built once per kh
            unsigned long long rr[12];
#pragma unroll
            for (int j = 0; j < 12; j++) rr[j] = pk2(rin[j], rin[j]);

#pragma unroll
            for (int kw = 0; kw < 5; kw++) {
                // weights for 8 channels = 4 packed pairs, direct LDS.128
                const ulonglong2* wp =
                    (const ulonglong2*)&s_w[(kh * 5 + kw) * 128 + og * 8];
                ulonglong2 wa = wp[0], wb = wp[1];
#pragma unroll
                for (int j = 0; j < 8; j++) {
                    acc2[0][j] = ffma2(wa.x, rr[kw + j], acc2[0][j]);
                    acc2[1][j] = ffma2(wa.y, rr[kw + j], acc2[1][j]);
                    acc2[2][j] = ffma2(wb.x, rr[kw + j], acc2[2][j]);
                    acc2[3][j] = ffma2(wb.y, rr[kw + j], acc2[3][j]);
                }
            }
        }
    }

    // write conv output: flat = n*1048576 + o*4096 + y*64 + x
    float* outp = g_conv + n * 1048576 + (obase + og * 8) * 4096
                + (hbase + hl) * 64 + wbase + wl;
#pragma unroll
    for (int p = 0; p < 4; p++) {
        float lo[8], hi[8];
#pragma unroll
        for (int j = 0; j < 8; j++) upk2(acc2[p][j], lo[j], hi[j]);
        float4 a0 = {lo[0], lo[1], lo[2], lo[3]};
        float4 a1 = {lo[4], lo[5], lo[6], lo[7]};
        float4 b0 = {hi[0], hi[1], hi[2], hi[3]};
        float4 b1 = {hi[4], hi[5], hi[6], hi[7]};
        float* r0 = outp + (2 * p) * 4096;
        float* r1 = outp + (2 * p + 1) * 4096;
        *(float4*)(r0)     = a0;
        *(float4*)(r0 + 4) = a1;
        *(float4*)(r1)     = b0;
        *(float4*)(r1 + 4) = b1;
    }
}

// ---------------------------------------------------------------------------
// routing: one warp per pixel. lane = a atom.
// iter0 softmax(0) == 1/8 exactly -> skip softmax + broadcasts.
// agreement via 32-value butterfly transpose-reduce (31 shfl instead of 160).
// ---------------------------------------------------------------------------
__global__ __launch_bounds__(256) void routing_kernel(const float* __restrict__ bias,
                                                      float* __restrict__ out) {
    const unsigned FULL = 0xffffffffu;
    int gwarp = (blockIdx.x * 256 + threadIdx.x) >> 5;
    int lane  = threadIdx.x & 31;
    int b  = gwarp >> 12;
    int hw = gwarp & 4095;

    const float* vb = g_conv + b * 4194304 + hw * 256 + lane;
    float v[4][8];
#pragma unroll
    for (int i = 0; i < 4; i++)
#pragma unroll
        for (int o = 0; o < 8; o++)
            v[i][o] = vb[i * 1048576 + o * 32];

    float bia[8];
#pragma unroll
    for (int o = 0; o < 8; o++) bia[o] = bias[o * 32 + lane];

    // lane l holds logits[i = l>>3][o = l&7]
    float logit = 0.f;
    float act[8];

#pragma unroll
    for (int it = 0; it < 3; it++) {
        float pre[8];
        if (it == 0) {
            // softmax of zeros == 1/8 for every (i,o)
#pragma unroll
            for (int o = 0; o < 8; o++) {
                float p = bia[o];
#pragma unroll
                for (int i = 0; i < 4; i++) p = fmaf(0.125f, v[i][o], p);
                pre[o] = p;
            }
        } else {
            // softmax over o within 8-lane groups
            float m = logit;
            m = fmaxf(m, __shfl_xor_sync(FULL, m, 1));
            m = fmaxf(m, __shfl_xor_sync(FULL, m, 2));
            m = fmaxf(m, __shfl_xor_sync(FULL, m, 4));
            float e = __expf(logit - m);
            float s = e;
            s += __shfl_xor_sync(FULL, s, 1);
            s += __shfl_xor_sync(FULL, s, 2);
            s += __shfl_xor_sync(FULL, s, 4);
            float route = e / s;
#pragma unroll
            for (int o = 0; o < 8; o++) {
                float p = bia[o];
#pragma unroll
                for (int i = 0; i < 4; i++) {
                    float r = __shfl_sync(FULL, route, i * 8 + o);
                    p = fmaf(r, v[i][o], p);
                }
                pre[o] = p;
            }
        }

        // squash per o (reduce pre^2 over all 32 lanes)
#pragma unroll
        for (int o = 0; o < 8; o++) {
            float sq = pre[o] * pre[o];
            sq += __shfl_xor_sync(FULL, sq, 1);
            sq += __shfl_xor_sync(FULL, sq, 2);
            sq += __shfl_xor_sync(FULL, sq, 4);
            sq += __shfl_xor_sync(FULL, sq, 8);
            sq += __shfl_xor_sync(FULL, sq, 16);
            float f = sq / ((1.f + sq) * sqrtf(sq + 1e-7f));
            act[o] = pre[o] * f;
        }

        if (it < 2) {
            // agreement[i][o] = sum_a v[i][o][a]*act[o][a], delivered to lane i*8+o
            float g[32];
#pragma unroll
            for (int i = 0; i < 4; i++)
#pragma unroll
                for (int o = 0; o < 8; o++)
                    g[i * 8 + o] = v[i][o] * act[o];

            int len = 32;
#pragma unroll
            for (int m = 16; m >= 1; m >>= 1) {
                int half = len >> 1;
                bool up = (lane & m) != 0;
#pragma unroll
                for (int k = 0; k < 16; k++) {
                    if (k < half) {
                        float send = up ? g[k] : g[k + half];
                        float keep = up ? g[k + half] : g[k];
                        g[k] = keep + __shfl_xor_sync(FULL, send, m);
                    }
                }
                len = half;
            }
            logit += g[0];
        }
    }

    // out (B, A=32, C=8, h, w)
    float* ob = out + ((b * 32 + lane) * 8) * 4096 + hw;
#pragma unroll
    for (int o = 0; o < 8; o++)
        ob[o * 4096] = act[o];
}

// ---------------------------------------------------------------------------
extern "C" void kernel_launch(void* const* d_in, const int* in_sizes, int n_in,
                              void* d_out, int out_size) {
    const float* x = (const float*)d_in[0];
    const float* W = (const float*)d_in[1];
    const float* b = (const float*)d_in[2];
    float* out = (float*)d_out;

    prep_t_kernel<<<8192, 256>>>(x);
    prep_w_kernel<<<400, 256>>>(W);
    conv_kernel<<<dim3(32, 2, 32), 256>>>();
    routing_kernel<<<4096, 256>>>(b, out);
}

// round 4
// speedup vs baseline: 1.2180x; 1.1045x over previous
#include <cuda_runtime.h>
#include <cuda_bf16.h>
#include <cstdint>

// ---------------------------------------------------------------------------
// Problem constants
//   x: (8, 16, 4, 64, 64) f32      A_IN=16, C_IN=4
//   W: (256, 16, 5, 5)    f32      C_OUT*A_OUT=256
//   b: (1, 1, 8, 32)      f32
//   out: (8, 32, 8, 64, 64) f32
// ---------------------------------------------------------------------------

static __device__ float g_t[32 * 16 * 64 * 64];              // conv input "t" (8 MB)
static __device__ __nv_bfloat16 g_wa_hi[2 * 16 * 128 * 32];  // W hi: [oh][ic][o128][k32]
static __device__ __nv_bfloat16 g_wa_lo[2 * 16 * 128 * 32];  // W lo residual
static __device__ float g_conv[32 * 256 * 64 * 64];          // conv output == votes (134 MB)

// ---------------- PTX helpers ----------------------------------------------
__device__ __forceinline__ uint32_t smem_u32(const void* p) {
    uint32_t a;
    asm("{ .reg .u64 t; cvta.to.shared.u64 t, %1; cvt.u32.u64 %0, t; }"
        : "=r"(a) : "l"(p));
    return a;
}
__device__ __forceinline__ void ldm_x4(uint32_t* r, uint32_t addr) {
    asm volatile("ldmatrix.sync.aligned.m8n8.x4.shared.b16 {%0,%1,%2,%3}, [%4];"
                 : "=r"(r[0]), "=r"(r[1]), "=r"(r[2]), "=r"(r[3]) : "r"(addr));
}
__device__ __forceinline__ void mma_bf16(float* c, const uint32_t* a,
                                         uint32_t b0, uint32_t b1) {
    asm volatile(
        "mma.sync.aligned.m16n8k16.row.col.f32.bf16.bf16.f32 "
        "{%0,%1,%2,%3}, {%4,%5,%6,%7}, {%8,%9}, {%0,%1,%2,%3};"
        : "+f"(c[0]), "+f"(c[1]), "+f"(c[2]), "+f"(c[3])
        : "r"(a[0]), "r"(a[1]), "r"(a[2]), "r"(a[3]), "r"(b0), "r"(b1));
}

// smem geometry (bytes): rows padded to 80B (40 bf16) -> conflict-free ldmatrix
#define AH_OFF 0
#define AL_OFF 10240
#define BH_OFF 20480
#define BL_OFF 30720
#define STAGE  40960   // 2 stages -> 81920 B dynamic smem

// ---------------------------------------------------------------------------
// prep_t: t_flat[j], j = (((ci*8+b)*64+h)*64+w)*16 + a  ==  x[b,a,ci,h,w]
// (raw reinterpret identical to the reference's reshape chain)
// ---------------------------------------------------------------------------
__global__ void prep_t_kernel(const float* __restrict__ x) {
    int j = blockIdx.x * 256 + threadIdx.x;
    int a  = j & 15;
    int w  = (j >> 4) & 63;
    int h  = (j >> 10) & 63;
    int nb = j >> 16;
    int ci = nb >> 3;
    int b  = nb & 7;
    g_t[j] = x[(((b * 16 + a) * 4 + ci) << 12) + (h << 6) + w];
}

// ---------------------------------------------------------------------------
// prep_wa: split weights into bf16 hi/lo, layout [oh][ic][o_local 128][k 32]
// k = kh*5+kw (25 real, pad zero to 32)
// ---------------------------------------------------------------------------
__global__ void prep_wa_kernel(const float* __restrict__ W) {
    int idx = blockIdx.x * 256 + threadIdx.x;   // 0..131071
    int k  = idx & 31;
    int ol = (idx >> 5) & 127;
    int ic = (idx >> 12) & 15;
    int oh = idx >> 16;
    float w = (k < 25) ? W[(oh * 128 + ol) * 400 + ic * 25 + k] : 0.f;
    __nv_bfloat16 hi = __float2bfloat16(w);
    float lof = w - __bfloat162float(hi);
    g_wa_hi[idx] = hi;
    g_wa_lo[idx] = __float2bfloat16(lof);
}

// ---------------------------------------------------------------------------
// conv via mma.sync bf16, 3-pass split (Ah*Bh + Ah*Bl + Al*Bh), fp32 accum.
// CTA: 128 o x 128 px (2 h-rows x 64 w). K: 16 ic-chunks of 32 (25 real).
// 8 warps: warp tile 64 o x 32 px -> 4 m-frags x 4 n-frags, acc 64 f32/thread.
// Double-buffered smem + register prefetch across the MMA stage.
// ---------------------------------------------------------------------------
__global__ __launch_bounds__(256) void conv_mma_kernel() {
    extern __shared__ char dsm[];
    const int pxt = blockIdx.x;   // 0..31  -> px base pxt*128 (h rows 2*pxt..)
    const int oh  = blockIdx.y;   // 0..1
    const int n   = blockIdx.z;   // 0..31
    const int tid = threadIdx.x;
    const int lane = tid & 31, wid = tid >> 5;
    const int wr = wid >> 2, wc = wid & 3;

    const uint32_t sb = smem_u32(dsm);

    // ldmatrix per-lane address offsets
    const int aRow = (lane & 7) + ((lane >> 3) & 1) * 8;
    const int aCol = (lane >> 4) * 8;
    const int bRow = (lane & 7) + (lane >> 4) * 8;
    const int bCol = ((lane >> 3) & 1) * 8;
    const uint32_t aAddr = sb + (uint32_t)((wr * 64 + aRow) * 80 + aCol * 2);
    const uint32_t bAddr = sb + (uint32_t)((wc * 32 + bRow) * 80 + bCol * 2);

    // fill roles: B gather -> thread owns (px = tid>>1, k-half = tid&1)
    const int bpx = tid >> 1, bkh = tid & 1;
    const int hh = pxt * 2 + (bpx >> 6), ww = bpx & 63;
    const float* tn = g_t + n * 65536;

    const __nv_bfloat16* gAh = g_wa_hi + oh * 16 * 4096;
    const __nv_bfloat16* gAl = g_wa_lo + oh * 16 * 4096;

    float acc[4][4][4];
#pragma unroll
    for (int mf = 0; mf < 4; mf++)
#pragma unroll
        for (int nf = 0; nf < 4; nf++)
#pragma unroll
            for (int q = 0; q < 4; q++) acc[mf][nf][q] = 0.f;

    uint4 pa[4];
    float bv[16];

    auto loadA = [&](int ic) {
        const uint4* ph = (const uint4*)(gAh + ic * 4096);
        const uint4* pl = (const uint4*)(gAl + ic * 4096);
        pa[0] = ph[tid];
        pa[1] = ph[tid + 256];
        pa[2] = pl[tid];
        pa[3] = pl[tid + 256];
    };
    auto loadB = [&](int ic) {
        const float* tp = tn + ic * 4096;
        if (bkh == 0) {
#pragma unroll
            for (int j = 0; j < 16; j++) {
                const int kh = j / 5, kw = j % 5;
                int y = hh + kh - 2, x = ww + kw - 2;
                bv[j] = ((unsigned)y < 64u && (unsigned)x < 64u)
                            ? __ldg(tp + y * 64 + x) : 0.f;
            }
        } else {
#pragma unroll
            for (int j = 0; j < 9; j++) {
                const int kk = 16 + j, kh = kk / 5, kw = kk % 5;
                int y = hh + kh - 2, x = ww + kw - 2;
                bv[j] = ((unsigned)y < 64u && (unsigned)x < 64u)
                            ? __ldg(tp + y * 64 + x) : 0.f;
            }
        }
    };
    auto stsAB = [&](int s) {
        char* base = dsm + s * STAGE;
        const int c0 = tid, c1 = tid + 256;
        *(uint4*)(base + AH_OFF + (c0 >> 2) * 80 + (c0 & 3) * 16) = pa[0];
        *(uint4*)(base + AH_OFF + (c1 >> 2) * 80 + (c1 & 3) * 16) = pa[1];
        *(uint4*)(base + AL_OFF + (c0 >> 2) * 80 + (c0 & 3) * 16) = pa[2];
        *(uint4*)(base + AL_OFF + (c1 >> 2) * 80 + (c1 & 3) * 16) = pa[3];
        char* bh = base + BH_OFF + bpx * 80;
        char* bl = base + BL_OFF + bpx * 80;
        if (bkh == 0) {
#pragma unroll
            for (int j = 0; j < 16; j++) {
                __nv_bfloat16 hi = __float2bfloat16(bv[j]);
                __nv_bfloat16 lo = __float2bfloat16(bv[j] - __bfloat162float(hi));
                *(__nv_bfloat16*)(bh + j * 2) = hi;
                *(__nv_bfloat16*)(bl + j * 2) = lo;
            }
        } else {
#pragma unroll
            for (int j = 0; j < 9; j++) {
                __nv_bfloat16 hi = __float2bfloat16(bv[j]);
                __nv_bfloat16 lo = __float2bfloat16(bv[j] - __bfloat162float(hi));
                *(__nv_bfloat16*)(bh + (16 + j) * 2) = hi;
                *(__nv_bfloat16*)(bl + (16 + j) * 2) = lo;
            }
            const __nv_bfloat16 z = __float2bfloat16(0.f);
#pragma unroll
            for (int kk = 25; kk < 32; kk++) {
                *(__nv_bfloat16*)(bh + kk * 2) = z;
                *(__nv_bfloat16*)(bl + kk * 2) = z;
            }
        }
    };

    loadA(0);
    loadB(0);
    stsAB(0);
    __syncthreads();

    for (int ic = 0; ic < 16; ic++) {
        const int s = ic & 1;
        if (ic < 15) { loadA(ic + 1); loadB(ic + 1); }

        const uint32_t stg = s * STAGE;
#pragma unroll
        for (int pass = 0; pass < 3; pass++) {
            const uint32_t aoff = stg + (pass < 2 ? AH_OFF : AL_OFF);
            const uint32_t boff = stg + (pass == 1 ? BL_OFF : BH_OFF);
#pragma unroll
            for (int ks = 0; ks < 2; ks++) {
                uint32_t a[4][4];
#pragma unroll
                for (int mf = 0; mf < 4; mf++)
                    ldm_x4(a[mf], aAddr + aoff + mf * 1280 + ks * 32);
                uint32_t b0[4], b1[4];
                ldm_x4(b0, bAddr + boff + ks * 32);
                ldm_x4(b1, bAddr + boff + 16 * 80 + ks * 32);
#pragma unroll
                for (int mf = 0; mf < 4; mf++) {
                    mma_bf16(acc[mf][0], a[mf], b0[0], b0[1]);
                    mma_bf16(acc[mf][1], a[mf], b0[2], b0[3]);
                    mma_bf16(acc[mf][2], a[mf], b1[0], b1[1]);
                    mma_bf16(acc[mf][3], a[mf], b1[2], b1[3]);
                }
            }
        }
        if (ic < 15) stsAB(s ^ 1);
        __syncthreads();
    }

    // epilogue: direct float2 stores into the flat [n][o][hw] layout
    const int g  = lane >> 2, t4 = lane & 3;
    float* outn = g_conv + n * 1048576;
    const int obase  = oh * 128 + wr * 64 + g;
    const int pxbase = pxt * 128 + wc * 32 + 2 * t4;
#pragma unroll
    for (int mf = 0; mf < 4; mf++) {
#pragma unroll
        for (int nf = 0; nf < 4; nf++) {
            float* p0 = outn + (obase + mf * 16) * 4096 + pxbase + nf * 8;
            *(float2*)p0 = make_float2(acc[mf][nf][0], acc[mf][nf][1]);
            *(float2*)(p0 + 8 * 4096) = make_float2(acc[mf][nf][2], acc[mf][nf][3]);
        }
    }
}

// ---------------------------------------------------------------------------
// routing: one warp per pixel. lane = a atom. (unchanged from R2)
// ---------------------------------------------------------------------------
__global__ __launch_bounds__(256) void routing_kernel(const float* __restrict__ bias,
                                                      float* __restrict__ out) {
    const unsigned FULL = 0xffffffffu;
    int gwarp = (blockIdx.x * 256 + threadIdx.x) >> 5;
    int lane  = threadIdx.x & 31;
    int b  = gwarp >> 12;
    int hw = gwarp & 4095;

    const float* vb = g_conv + b * 4194304 + hw * 256 + lane;
    float v[4][8];
#pragma unroll
    for (int i = 0; i < 4; i++)
#pragma unroll
        for (int o = 0; o < 8; o++)
            v[i][o] = vb[i * 1048576 + o * 32];

    float bia[8];
#pragma unroll
    for (int o = 0; o < 8; o++) bia[o] = bias[o * 32 + lane];

    float logit = 0.f;
    float act[8];

#pragma unroll
    for (int it = 0; it < 3; it++) {
        float pre[8];
        if (it == 0) {
#pragma unroll
            for (int o = 0; o < 8; o++) {
                float p = bia[o];
#pragma unroll
                for (int i = 0; i < 4; i++) p = fmaf(0.125f, v[i][o], p);
                pre[o] = p;
            }
        } else {
            float m = logit;
            m = fmaxf(m, __shfl_xor_sync(FULL, m, 1));
            m = fmaxf(m, __shfl_xor_sync(FULL, m, 2));
            m = fmaxf(m, __shfl_xor_sync(FULL, m, 4));
            float e = __expf(logit - m);
            float ssum = e;
            ssum += __shfl_xor_sync(FULL, ssum, 1);
            ssum += __shfl_xor_sync(FULL, ssum, 2);
            ssum += __shfl_xor_sync(FULL, ssum, 4);
            float route = e / ssum;
#pragma unroll
            for (int o = 0; o < 8; o++) {
                float p = bia[o];
#pragma unroll
                for (int i = 0; i < 4; i++) {
                    float r = __shfl_sync(FULL, route, i * 8 + o);
                    p = fmaf(r, v[i][o], p);
                }
                pre[o] = p;
            }
        }

#pragma unroll
        for (int o = 0; o < 8; o++) {
            float sq = pre[o] * pre[o];
            sq += __shfl_xor_sync(FULL, sq, 1);
            sq += __shfl_xor_sync(FULL, sq, 2);
            sq += __shfl_xor_sync(FULL, sq, 4);
            sq += __shfl_xor_sync(FULL, sq, 8);
            sq += __shfl_xor_sync(FULL, sq, 16);
            float f = sq / ((1.f + sq) * sqrtf(sq + 1e-7f));
            act[o] = pre[o] * f;
        }

        if (it < 2) {
            float g[32];
#pragma unroll
            for (int i = 0; i < 4; i++)
#pragma unroll
                for (int o = 0; o < 8; o++)
                    g[i * 8 + o] = v[i][o] * act[o];

            int len = 32;
#pragma unroll
            for (int m = 16; m >= 1; m >>= 1) {
                int half = len >> 1;
                bool up = (lane & m) != 0;
#pragma unroll
                for (int k = 0; k < 16; k++) {
                    if (k < half) {
                        float send = up ? g[k] : g[k + half];
                        float keep = up ? g[k + half] : g[k];
                        g[k] = keep + __shfl_xor_sync(FULL, send, m);
                    }
                }
                len = half;
            }
            logit += g[0];
        }
    }

    float* ob = out + ((b * 32 + lane) * 8) * 4096 + hw;
#pragma unroll
    for (int o = 0; o < 8; o++)
        ob[o * 4096] = act[o];
}

// ---------------------------------------------------------------------------
extern "C" void kernel_launch(void* const* d_in, const int* in_sizes, int n_in,
                              void* d_out, int out_size) {
    const float* x = (const float*)d_in[0];
    const float* W = (const float*)d_in[1];
    const float* b = (const float*)d_in[2];
    float* out = (float*)d_out;

    static const int SMEM_BYTES = 2 * STAGE;   // 81920
    cudaFuncSetAttribute(conv_mma_kernel,
                         cudaFuncAttributeMaxDynamicSharedMemorySize, SMEM_BYTES);

    prep_t_kernel<<<8192, 256>>>(x);
    prep_wa_kernel<<<512, 256>>>(W);
    conv_mma_kernel<<<dim3(32, 2, 32), 256, SMEM_BYTES>>>();
    routing_kernel<<<4096, 256>>>(b, out);
}

// round 5
// speedup vs baseline: 2.2043x; 1.8098x over previous
#include <cuda_runtime.h>
#include <cuda_bf16.h>
#include <cstdint>

// ---------------------------------------------------------------------------
// Problem constants
//   x: (8, 16, 4, 64, 64) f32      A_IN=16, C_IN=4
//   W: (256, 16, 5, 5)    f32      C_OUT*A_OUT=256
//   b: (1, 1, 8, 32)      f32
//   out: (8, 32, 8, 64, 64) f32
// ---------------------------------------------------------------------------

static __device__ float g_t[32 * 16 * 64 * 64];            // conv input "t" (8 MB)
static __device__ __nv_bfloat16 g_wA[25 * 256 * 32];       // [pos][o][hi16|lo16]
static __device__ float g_conv[32 * 256 * 64 * 64];        // conv output == votes (134 MB)

// ---------------- PTX helpers ----------------------------------------------
__device__ __forceinline__ uint32_t smem_u32(const void* p) {
    uint32_t a;
    asm("{ .reg .u64 t; cvta.to.shared.u64 t, %1; cvt.u32.u64 %0, t; }"
        : "=r"(a) : "l"(p));
    return a;
}
__device__ __forceinline__ void ldm_x4(uint32_t* r, uint32_t addr) {
    asm volatile("ldmatrix.sync.aligned.m8n8.x4.shared.b16 {%0,%1,%2,%3}, [%4];"
                 : "=r"(r[0]), "=r"(r[1]), "=r"(r[2]), "=r"(r[3]) : "r"(addr));
}
__device__ __forceinline__ void mma_bf16(float* c, const uint32_t* a,
                                         uint32_t b0, uint32_t b1) {
    asm volatile(
        "mma.sync.aligned.m16n8k16.row.col.f32.bf16.bf16.f32 "
        "{%0,%1,%2,%3}, {%4,%5,%6,%7}, {%8,%9}, {%0,%1,%2,%3};"
        : "+f"(c[0]), "+f"(c[1]), "+f"(c[2]), "+f"(c[3])
        : "r"(a[0]), "r"(a[1]), "r"(a[2]), "r"(a[3]), "r"(b0), "r"(b1));
}

// smem layout (bytes). Rows pitch 80B: [hi 32B][lo 32B][pad 16B] -> 16B-aligned
// rows, conflict-free ldmatrix (80B = 20 words; 20*k mod 32 distinct for k<8).
#define A0_OFF 0
#define A1_OFF 10240
#define B_OFF  20480
#define SMEM_BYTES 53248   // 20480 + 6*68*80 = 53120, rounded up

// ---------------------------------------------------------------------------
// prep_t: t_flat[j], j = (((ci*8+b)*64+h)*64+w)*16 + a  ==  x[b,a,ci,h,w]
// (raw reinterpret identical to the reference's reshape chain)
// ---------------------------------------------------------------------------
__global__ void prep_t_kernel(const float* __restrict__ x) {
    int j = blockIdx.x * 256 + threadIdx.x;
    int a  = j & 15;
    int w  = (j >> 4) & 63;
    int h  = (j >> 10) & 63;
    int nb = j >> 16;
    int ci = nb >> 3;
    int b  = nb & 7;
    g_t[j] = x[(((b * 16 + a) * 4 + ci) << 12) + (h << 6) + w];
}

// ---------------------------------------------------------------------------
// prep_wA: per position pos=(kh*5+kw): A[o][ic] = W[o, ic, kh, kw], split into
// bf16 hi/lo: g_wA[pos][o][0..15] = hi(ic), [16..31] = lo(ic).
// ---------------------------------------------------------------------------
__global__ void prep_wA_kernel(const float* __restrict__ W) {
    int idx = blockIdx.x * 256 + threadIdx.x;   // 0..102399
    int ic  = idx & 15;
    int o   = (idx >> 4) & 255;
    int pos = idx >> 12;
    float w = W[o * 400 + ic * 25 + pos];
    __nv_bfloat16 hi = __float2bfloat16(w);
    __nv_bfloat16 lo = __float2bfloat16(w - __bfloat162float(hi));
    __nv_bfloat16* dst = g_wA + (pos * 256 + o) * 32 + ic;
    dst[0]  = hi;
    dst[16] = lo;
}

// ---------------------------------------------------------------------------
// conv: 25 shifted GEMMs, K=16 (=ic), bf16 3-pass split, fp32 accum.
// CTA: 128 o (oh half) x 128 px (2 h-rows x 64 w), one n.
// B: halo tile 6 rows x 68 cols x 16 ic, hi/lo, loaded ONCE per CTA.
// A: per-position [128 o x 16 ic] hi/lo, double-buffered.
// 8 warps: warp tile 64 o x 32 px.
// ---------------------------------------------------------------------------
__global__ __launch_bounds__(256, 2) void conv_mma_kernel() {
    extern __shared__ char dsm[];
    const int pxt = blockIdx.x;   // 0..31 -> h rows 2*pxt, 2*pxt+1
    const int oh  = blockIdx.y;   // 0..1
    const int n   = blockIdx.z;   // 0..31
    const int tid = threadIdx.x;
    const int lane = tid & 31, wid = tid >> 5;
    const int wr = wid >> 2, wc = wid & 3;
    const int lh = wc >> 1, wwbase = (wc & 1) * 32;

    const uint32_t sb = smem_u32(dsm);
    const int hbase = pxt * 2;

    // ldmatrix per-lane patterns (same as validated R4)
    const int aRow = (lane & 7) + ((lane >> 3) & 1) * 8;
    const int aCol = (lane >> 4) * 8;
    const int bRow = (lane & 7) + (lane >> 4) * 8;
    const int bCol = ((lane >> 3) & 1) * 8;
    const uint32_t aStat = (uint32_t)((wr * 64 + aRow) * 80 + aCol * 2);
    const uint32_t bStat = (uint32_t)(bRow * 80 + bCol * 2);

    // ---- B halo fill (once): rows r=0..5 (y=hbase+r-2), cols c=0..67 ------
    {
        const float* tn = g_t + n * 65536;
#pragma unroll
        for (int base = tid; base < 408; base += 256) {
            int r = base / 68, c = base % 68;
            int y = hbase + r - 2;
            int x = c - 2;
            bool ok = ((unsigned)y < 64u) && ((unsigned)x < 64u);
            char* row = dsm + B_OFF + base * 80;
            const float* src = tn + y * 64 + x;
#pragma unroll
            for (int ic = 0; ic < 16; ic++) {
                float v = ok ? __ldg(src + ic * 4096) : 0.f;
                __nv_bfloat16 hi = __float2bfloat16(v);
                __nv_bfloat16 lo = __float2bfloat16(v - __bfloat162float(hi));
                *(__nv_bfloat16*)(row + ic * 2)      = hi;
                *(__nv_bfloat16*)(row + 32 + ic * 2) = lo;
            }
        }
    }

    // ---- A fill helpers: 128 o x 64B per position = 512 uint4 ------------
    const uint4* gA = (const uint4*)g_wA;
    uint4 pre0, pre1;
    auto loadA = [&](int pos) {
        int f0 = tid, f1 = tid + 256;
        pre0 = gA[pos * 1024 + oh * 512 + f0];
        pre1 = gA[pos * 1024 + oh * 512 + f1];
    };
    auto stsA = [&](int buf) {
        char* base = dsm + (buf ? A1_OFF : A0_OFF);
        int f0 = tid, f1 = tid + 256;
        *(uint4*)(base + (f0 >> 2) * 80 + (f0 & 3) * 16) = pre0;
        *(uint4*)(base + (f1 >> 2) * 80 + (f1 & 3) * 16) = pre1;
    };

    float acc[4][4][4];
#pragma unroll
    for (int mf = 0; mf < 4; mf++)
#pragma unroll
        for (int nf = 0; nf < 4; nf++)
#pragma unroll
            for (int q = 0; q < 4; q++) acc[mf][nf][q] = 0.f;

    loadA(0);
    stsA(0);
    __syncthreads();

#pragma unroll 1
    for (int pos = 0; pos < 25; pos++) {
        const int kh = pos / 5, kw = pos - kh * 5;
        if (pos < 24) loadA(pos + 1);

        const uint32_t Ab = sb + ((pos & 1) ? A1_OFF : A0_OFF) + aStat;
        const uint32_t Bb = sb + B_OFF
            + (uint32_t)(((lh + kh) * 68 + wwbase + kw) * 80) + bStat;

        uint32_t a4[4][4], bh[2][4], bl[2][4];
#pragma unroll
        for (int mf = 0; mf < 4; mf++) ldm_x4(a4[mf], Ab + mf * 1280);
        ldm_x4(bh[0], Bb);
        ldm_x4(bh[1], Bb + 16 * 80);
        ldm_x4(bl[0], Bb + 32);
        ldm_x4(bl[1], Bb + 16 * 80 + 32);

        // pass 0: Ah * Bh
#pragma unroll
        for (int mf = 0; mf < 4; mf++) {
            mma_bf16(acc[mf][0], a4[mf], bh[0][0], bh[0][1]);
            mma_bf16(acc[mf][1], a4[mf], bh[0][2], bh[0][3]);
            mma_bf16(acc[mf][2], a4[mf], bh[1][0], bh[1][1]);
            mma_bf16(acc[mf][3], a4[mf], bh[1][2], bh[1][3]);
        }
        // pass 1: Ah * Bl
#pragma unroll
        for (int mf = 0; mf < 4; mf++) {
            mma_bf16(acc[mf][0], a4[mf], bl[0][0], bl[0][1]);
            mma_bf16(acc[mf][1], a4[mf], bl[0][2], bl[0][3]);
            mma_bf16(acc[mf][2], a4[mf], bl[1][0], bl[1][1]);
            mma_bf16(acc[mf][3], a4[mf], bl[1][2], bl[1][3]);
        }
        // pass 2: Al * Bh  (reload A frags as lo: +32B within row)
#pragma unroll
        for (int mf = 0; mf < 4; mf++) ldm_x4(a4[mf], Ab + mf * 1280 + 32);
#pragma unroll
        for (int mf = 0; mf < 4; mf++) {
            mma_bf16(acc[mf][0], a4[mf], bh[0][0], bh[0][1]);
            mma_bf16(acc[mf][1], a4[mf], bh[0][2], bh[0][3]);
            mma_bf16(acc[mf][2], a4[mf], bh[1][0], bh[1][1]);
            mma_bf16(acc[mf][3], a4[mf], bh[1][2], bh[1][3]);
        }

        if (pos < 24) stsA((pos + 1) & 1);
        __syncthreads();
    }

    // ---- epilogue: direct float2 stores into flat [n][o][hw] --------------
    const int g  = lane >> 2, t4 = lane & 3;
    float* outn = g_conv + n * 1048576;
    const int obase  = oh * 128 + wr * 64 + g;
    const int pxbase = pxt * 128 + wc * 32 + 2 * t4;
#pragma unroll
    for (int mf = 0; mf < 4; mf++) {
#pragma unroll
        for (int nf = 0; nf < 4; nf++) {
            float* p0 = outn + (obase + mf * 16) * 4096 + pxbase + nf * 8;
            *(float2*)p0 = make_float2(acc[mf][nf][0], acc[mf][nf][1]);
            *(float2*)(p0 + 8 * 4096) = make_float2(acc[mf][nf][2], acc[mf][nf][3]);
        }
    }
}

// ---------------------------------------------------------------------------
// routing: one warp per pixel. lane = a atom.
// squash sums via butterfly transpose-reduce: 9 shfl + 8 broadcasts (was 40).
// ---------------------------------------------------------------------------
__global__ __launch_bounds__(256) void routing_kernel(const float* __restrict__ bias,
                                                      float* __restrict__ out) {
    const unsigned FULL = 0xffffffffu;
    int gwarp = (blockIdx.x * 256 + threadIdx.x) >> 5;
    int lane  = threadIdx.x & 31;
    int b  = gwarp >> 12;
    int hw = gwarp & 4095;

    const float* vb = g_conv + b * 4194304 + hw * 256 + lane;
    float v[4][8];
#pragma unroll
    for (int i = 0; i < 4; i++)
#pragma unroll
        for (int o = 0; o < 8; o++)
            v[i][o] = vb[i * 1048576 + o * 32];

    float bia[8];
#pragma unroll
    for (int o = 0; o < 8; o++) bia[o] = bias[o * 32 + lane];

    float logit = 0.f;
    float act[8];

#pragma unroll
    for (int it = 0; it < 3; it++) {
        float pre[8];
        if (it == 0) {
#pragma unroll
            for (int o = 0; o < 8; o++) {
                float p = bia[o];
#pragma unroll
                for (int i = 0; i < 4; i++) p = fmaf(0.125f, v[i][o], p);
                pre[o] = p;
            }
        } else {
            float m = logit;
            m = fmaxf(m, __shfl_xor_sync(FULL, m, 1));
            m = fmaxf(m, __shfl_xor_sync(FULL, m, 2));
            m = fmaxf(m, __shfl_xor_sync(FULL, m, 4));
            float e = __expf(logit - m);
            float ssum = e;
            ssum += __shfl_xor_sync(FULL, ssum, 1);
            ssum += __shfl_xor_sync(FULL, ssum, 2);
            ssum += __shfl_xor_sync(FULL, ssum, 4);
            float route = e / ssum;
#pragma unroll
            for (int o = 0; o < 8; o++) {
                float p = bia[o];
#pragma unroll
                for (int i = 0; i < 4; i++) {
                    float r = __shfl_sync(FULL, route, i * 8 + o);
                    p = fmaf(r, v[i][o], p);
                }
                pre[o] = p;
            }
        }

        // squash: S[o] = sum over 32 lanes of pre[o]^2 via transpose-reduce.
        {
            float g8[8];
#pragma unroll
            for (int o = 0; o < 8; o++) g8[o] = pre[o] * pre[o];
            {   // m=16: keep idx bit2
                bool up = (lane & 16) != 0;
#pragma unroll
                for (int k = 0; k < 4; k++) {
                    float send = up ? g8[k] : g8[k + 4];
                    float keep = up ? g8[k + 4] : g8[k];
                    g8[k] = keep + __shfl_xor_sync(FULL, send, 16);
                }
            }
            {   // m=8: idx bit1
                bool up = (lane & 8) != 0;
#pragma unroll
                for (int k = 0; k < 2; k++) {
                    float send = up ? g8[k] : g8[k + 2];
                    float keep = up ? g8[k + 2] : g8[k];
                    g8[k] = keep + __shfl_xor_sync(FULL, send, 8);
                }
            }
            {   // m=4: idx bit0
                bool up = (lane & 4) != 0;
                float send = up ? g8[0] : g8[1];
                float keep = up ? g8[1] : g8[0];
                g8[0] = keep + __shfl_xor_sync(FULL, send, 4);
            }
            g8[0] += __shfl_xor_sync(FULL, g8[0], 2);
            g8[0] += __shfl_xor_sync(FULL, g8[0], 1);
            // lane l holds S[(l>>2)&7]; gather all 8 per lane
#pragma unroll
            for (int o = 0; o < 8; o++) {
                float S = __shfl_sync(FULL, g8[0], (o << 2) | (lane & 3));
                float f = S / ((1.f + S) * sqrtf(S + 1e-7f));
                act[o] = pre[o] * f;
            }
        }

        if (it < 2) {
            float g[32];
#pragma unroll
            for (int i = 0; i < 4; i++)
#pragma unroll
                for (int o = 0; o < 8; o++)
                    g[i * 8 + o] = v[i][o] * act[o];

            int len = 32;
#pragma unroll
            for (int m = 16; m >= 1; m >>= 1) {
                int half = len >> 1;
                bool up = (lane & m) != 0;
#pragma unroll
                for (int k = 0; k < 16; k++) {
                    if (k < half) {
                        float send = up ? g[k] : g[k + half];
                        float keep = up ? g[k + half] : g[k];
                        g[k] = keep + __shfl_xor_sync(FULL, send, m);
                    }
                }
                len = half;
            }
            logit += g[0];
        }
    }

    float* ob = out + ((b * 32 + lane) * 8) * 4096 + hw;
#pragma unroll
    for (int o = 0; o < 8; o++)
        ob[o * 4096] = act[o];
}

// ---------------------------------------------------------------------------
extern "C" void kernel_launch(void* const* d_in, const int* in_sizes, int n_in,
                              void* d_out, int out_size) {
    const float* x = (const float*)d_in[0];
    const float* W = (const float*)d_in[1];
    const float* b = (const float*)d_in[2];
    float* out = (float*)d_out;

    cudaFuncSetAttribute(conv_mma_kernel,
                         cudaFuncAttributeMaxDynamicSharedMemorySize, SMEM_BYTES);

    prep_t_kernel<<<8192, 256>>>(x);
    prep_wA_kernel<<<400, 256>>>(W);
    conv_mma_kernel<<<dim3(32, 2, 32), 256, SMEM_BYTES>>>();
    routing_kernel<<<4096, 256>>>(b, out);
}

// round 6
// speedup vs baseline: 2.6557x; 1.2048x over previous
#include <cuda_runtime.h>
#include <cuda_fp16.h>
#include <cstdint>

// ---------------------------------------------------------------------------
// Problem constants
//   x: (8, 16, 4, 64, 64) f32      A_IN=16, C_IN=4
//   W: (256, 16, 5, 5)    f32      C_OUT*A_OUT=256
//   b: (1, 1, 8, 32)      f32
//   out: (8, 32, 8, 64, 64) f32
// ---------------------------------------------------------------------------

static __device__ float g_t[32 * 16 * 64 * 64];      // conv input "t" (8 MB)
static __device__ __half g_wA[25 * 256 * 32];        // [pos][o][hi16|lo16] fp16
static __device__ float g_conv[32 * 256 * 64 * 64];  // conv output == votes (134 MB)

// ---------------- PTX helpers ----------------------------------------------
__device__ __forceinline__ uint32_t smem_u32(const void* p) {
    uint32_t a;
    asm("{ .reg .u64 t; cvta.to.shared.u64 t, %1; cvt.u32.u64 %0, t; }"
        : "=r"(a) : "l"(p));
    return a;
}
__device__ __forceinline__ void ldm_x4(uint32_t* r, uint32_t addr) {
    asm volatile("ldmatrix.sync.aligned.m8n8.x4.shared.b16 {%0,%1,%2,%3}, [%4];"
                 : "=r"(r[0]), "=r"(r[1]), "=r"(r[2]), "=r"(r[3]) : "r"(addr));
}
__device__ __forceinline__ void mma_fp16(float* c, const uint32_t* a,
                                         uint32_t b0, uint32_t b1) {
    asm volatile(
        "mma.sync.aligned.m16n8k16.row.col.f32.f16.f16.f32 "
        "{%0,%1,%2,%3}, {%4,%5,%6,%7}, {%8,%9}, {%0,%1,%2,%3};"
        : "+f"(c[0]), "+f"(c[1]), "+f"(c[2]), "+f"(c[3])
        : "r"(a[0]), "r"(a[1]), "r"(a[2]), "r"(a[3]), "r"(b0), "r"(b1));
}

// smem (bytes): A rows pitch 80 ([hi 32][lo 32][pad 16]); B rows pitch 48
// ([16 fp16 = 32B][pad 16]). Both pitches give 8 distinct 16B phases mod 128
// -> conflict-free ldmatrix.
#define A0_OFF 0
#define A1_OFF 10240
#define B_OFF  20480
#define SMEM_BYTES 40960   // 20480 + 408*48 = 40064, rounded

// ---------------------------------------------------------------------------
// prep_t: t_flat[j], j = (((ci*8+b)*64+h)*64+w)*16 + a  ==  x[b,a,ci,h,w]
// ---------------------------------------------------------------------------
__global__ void prep_t_kernel(const float* __restrict__ x) {
    int j = blockIdx.x * 256 + threadIdx.x;
    int a  = j & 15;
    int w  = (j >> 4) & 63;
    int h  = (j >> 10) & 63;
    int nb = j >> 16;
    int ci = nb >> 3;
    int b  = nb & 7;
    g_t[j] = x[(((b * 16 + a) * 4 + ci) << 12) + (h << 6) + w];
}

// ---------------------------------------------------------------------------
// prep_wA: per pos: A[o][ic] = W[o, ic, kh, kw], fp16 hi/lo split.
// ---------------------------------------------------------------------------
__global__ void prep_wA_kernel(const float* __restrict__ W) {
    int idx = blockIdx.x * 256 + threadIdx.x;   // 0..102399
    int ic  = idx & 15;
    int o   = (idx >> 4) & 255;
    int pos = idx >> 12;
    float w = W[o * 400 + ic * 25 + pos];
    __half hi = __float2half_rn(w);
    __half lo = __float2half_rn(w - __half2float(hi));
    __half* dst = g_wA + (pos * 256 + o) * 32 + ic;
    dst[0]  = hi;
    dst[16] = lo;
}

// ---------------------------------------------------------------------------
// conv: 25 shifted GEMMs, K=16, fp16 2-pass (Ah*B + Al*B), fp32 accum.
// CTA: 128 o (oh half) x 128 px (2 h-rows x 64 w), one n.
// B: halo 6 x 68 x 16ic fp16 (single), loaded once. A: per-pos, double-buf.
// ---------------------------------------------------------------------------
__global__ __launch_bounds__(256, 2) void conv_mma_kernel() {
    extern __shared__ char dsm[];
    const int pxt = blockIdx.x;   // 0..31 -> h rows 2*pxt, 2*pxt+1
    const int oh  = blockIdx.y;   // 0..1
    const int n   = blockIdx.z;   // 0..31
    const int tid = threadIdx.x;
    const int lane = tid & 31, wid = tid >> 5;
    const int wr = wid >> 2, wc = wid & 3;
    const int lh = wc >> 1, wwbase = (wc & 1) * 32;

    const uint32_t sb = smem_u32(dsm);
    const int hbase = pxt * 2;

    const int aRow = (lane & 7) + ((lane >> 3) & 1) * 8;
    const int aCol = (lane >> 4) * 8;
    const int bRow = (lane & 7) + (lane >> 4) * 8;
    const int bCol = ((lane >> 3) & 1) * 8;
    const uint32_t aStat = (uint32_t)((wr * 64 + aRow) * 80 + aCol * 2);
    const uint32_t bStat = (uint32_t)(bRow * 48 + bCol * 2);

    // ---- B halo fill (once): rows r=0..5 (y=hbase+r-2), cols c=0..67 ------
    {
        const float* tn = g_t + n * 65536;
#pragma unroll
        for (int base = tid; base < 408; base += 256) {
            int r = base / 68, c = base % 68;
            int y = hbase + r - 2;
            int x = c - 2;
            bool ok = ((unsigned)y < 64u) && ((unsigned)x < 64u);
            __half* row = (__half*)(dsm + B_OFF + base * 48);
            const float* src = tn + y * 64 + x;
#pragma unroll
            for (int ic = 0; ic < 16; ic++) {
                float v = ok ? __ldg(src + ic * 4096) : 0.f;
                row[ic] = __float2half_rn(v);
            }
        }
    }

    // ---- A fill: 128 o x 64B per position = 512 uint4 --------------------
    const uint4* gA = (const uint4*)g_wA;
    uint4 pre0, pre1;
    auto loadA = [&](int pos) {
        pre0 = gA[pos * 1024 + oh * 512 + tid];
        pre1 = gA[pos * 1024 + oh * 512 + tid + 256];
    };
    auto stsA = [&](int buf) {
        char* base = dsm + (buf ? A1_OFF : A0_OFF);
        int f0 = tid, f1 = tid + 256;
        *(uint4*)(base + (f0 >> 2) * 80 + (f0 & 3) * 16) = pre0;
        *(uint4*)(base + (f1 >> 2) * 80 + (f1 & 3) * 16) = pre1;
    };

    float acc[4][4][4];
#pragma unroll
    for (int mf = 0; mf < 4; mf++)
#pragma unroll
        for (int nf = 0; nf < 4; nf++)
#pragma unroll
            for (int q = 0; q < 4; q++) acc[mf][nf][q] = 0.f;

    loadA(0);
    stsA(0);
    __syncthreads();

#pragma unroll 1
    for (int pos = 0; pos < 25; pos++) {
        const int kh = pos / 5, kw = pos - kh * 5;
        if (pos < 24) loadA(pos + 1);

        const uint32_t Ab = sb + ((pos & 1) ? A1_OFF : A0_OFF) + aStat;
        const uint32_t Bb = sb + B_OFF
            + (uint32_t)(((lh + kh) * 68 + wwbase + kw) * 48) + bStat;

        uint32_t a4[4][4], bh[2][4];
#pragma unroll
        for (int mf = 0; mf < 4; mf++) ldm_x4(a4[mf], Ab + mf * 1280);
        ldm_x4(bh[0], Bb);
        ldm_x4(bh[1], Bb + 16 * 48);

        // pass 0: Ah * B
#pragma unroll
        for (int mf = 0; mf < 4; mf++) {
            mma_fp16(acc[mf][0], a4[mf], bh[0][0], bh[0][1]);
            mma_fp16(acc[mf][1], a4[mf], bh[0][2], bh[0][3]);
            mma_fp16(acc[mf][2], a4[mf], bh[1][0], bh[1][1]);
            mma_fp16(acc[mf][3], a4[mf], bh[1][2], bh[1][3]);
        }
        // pass 1: Al * B  (A frags reloaded from +32B within row)
#pragma unroll
        for (int mf = 0; mf < 4; mf++) ldm_x4(a4[mf], Ab + mf * 1280 + 32);
#pragma unroll
        for (int mf = 0; mf < 4; mf++) {
            mma_fp16(acc[mf][0], a4[mf], bh[0][0], bh[0][1]);
            mma_fp16(acc[mf][1], a4[mf], bh[0][2], bh[0][3]);
            mma_fp16(acc[mf][2], a4[mf], bh[1][0], bh[1][1]);
            mma_fp16(acc[mf][3], a4[mf], bh[1][2], bh[1][3]);
        }

        if (pos < 24) stsA((pos + 1) & 1);
        __syncthreads();
    }

    // ---- epilogue: direct float2 stores into flat [n][o][hw] --------------
    const int g  = lane >> 2, t4 = lane & 3;
    float* outn = g_conv + n * 1048576;
    const int obase  = oh * 128 + wr * 64 + g;
    const int pxbase = pxt * 128 + wc * 32 + 2 * t4;
#pragma unroll
    for (int mf = 0; mf < 4; mf++) {
#pragma unroll
        for (int nf = 0; nf < 4; nf++) {
            float* p0 = outn + (obase + mf * 16) * 4096 + pxbase + nf * 8;
            *(float2*)p0 = make_float2(acc[mf][nf][0], acc[mf][nf][1]);
            *(float2*)(p0 + 8 * 4096) = make_float2(acc[mf][nf][2], acc[mf][nf][3]);
        }
    }
}

// ---------------------------------------------------------------------------
// routing: one warp per pixel. lane = a atom. bias in smem; agreement products
// folded into butterfly level 1 (peak live array 16, not 32); <=64 regs.
// ---------------------------------------------------------------------------
__global__ __launch_bounds__(256, 4) void routing_kernel(const float* __restrict__ bias,
                                                         float* __restrict__ out) {
    const unsigned FULL = 0xffffffffu;
    __shared__ float s_bias[256];
    s_bias[threadIdx.x] = bias[threadIdx.x];
    __syncthreads();

    int gwarp = (blockIdx.x * 256 + threadIdx.x) >> 5;
    int lane  = threadIdx.x & 31;
    int b  = gwarp >> 12;
    int hw = gwarp & 4095;

    const float* vb = g_conv + b * 4194304 + hw * 256 + lane;
    float v[4][8];
#pragma unroll
    for (int i = 0; i < 4; i++)
#pragma unroll
        for (int o = 0; o < 8; o++)
            v[i][o] = vb[i * 1048576 + o * 32];

    float logit = 0.f;
    float act[8];

#pragma unroll
    for (int it = 0; it < 3; it++) {
        float pre[8];
        if (it == 0) {
#pragma unroll
            for (int o = 0; o < 8; o++) {
                float p = s_bias[o * 32 + lane];
#pragma unroll
                for (int i = 0; i < 4; i++) p = fmaf(0.125f, v[i][o], p);
                pre[o] = p;
            }
        } else {
            float m = logit;
            m = fmaxf(m, __shfl_xor_sync(FULL, m, 1));
            m = fmaxf(m, __shfl_xor_sync(FULL, m, 2));
            m = fmaxf(m, __shfl_xor_sync(FULL, m, 4));
            float e = __expf(logit - m);
            float ssum = e;
            ssum += __shfl_xor_sync(FULL, ssum, 1);
            ssum += __shfl_xor_sync(FULL, ssum, 2);
            ssum += __shfl_xor_sync(FULL, ssum, 4);
            float route = e / ssum;
#pragma unroll
            for (int o = 0; o < 8; o++) {
                float p = s_bias[o * 32 + lane];
#pragma unroll
                for (int i = 0; i < 4; i++) {
                    float r = __shfl_sync(FULL, route, i * 8 + o);
                    p = fmaf(r, v[i][o], p);
                }
                pre[o] = p;
            }
        }

        // squash: S[o] = sum_32 pre[o]^2 via transpose-reduce (validated R5)
        {
            float g8[8];
#pragma unroll
            for (int o = 0; o < 8; o++) g8[o] = pre[o] * pre[o];
            {
                bool up = (lane & 16) != 0;
#pragma unroll
                for (int k = 0; k < 4; k++) {
                    float send = up ? g8[k] : g8[k + 4];
                    float keep = up ? g8[k + 4] : g8[k];
                    g8[k] = keep + __shfl_xor_sync(FULL, send, 16);
                }
            }
            {
                bool up = (lane & 8) != 0;
#pragma unroll
                for (int k = 0; k < 2; k++) {
                    float send = up ? g8[k] : g8[k + 2];
                    float keep = up ? g8[k + 2] : g8[k];
                    g8[k] = keep + __shfl_xor_sync(FULL, send, 8);
                }
            }
            {
                bool up = (lane & 4) != 0;
                float send = up ? g8[0] : g8[1];
                float keep = up ? g8[1] : g8[0];
                g8[0] = keep + __shfl_xor_sync(FULL, send, 4);
            }
            g8[0] += __shfl_xor_sync(FULL, g8[0], 2);
            g8[0] += __shfl_xor_sync(FULL, g8[0], 1);
#pragma unroll
            for (int o = 0; o < 8; o++) {
                float S = __shfl_sync(FULL, g8[0], (o << 2) | (lane & 3));
                float f = S / ((1.f + S) * sqrtf(S + 1e-7f));
                act[o] = pre[o] * f;
            }
        }

        if (it < 2) {
            // agreement: fold v*act products into butterfly level m=16
            float g16[16];
            {
                bool up = (lane & 16) != 0;
#pragma unroll
                for (int k = 0; k < 16; k++) {
                    int i = k >> 3, o = k & 7;
                    float pk  = v[i][o] * act[o];
                    float pk2 = v[i + 2][o] * act[o];
                    float send = up ? pk : pk2;
                    float keep = up ? pk2 : pk;
                    g16[k] = keep + __shfl_xor_sync(FULL, send, 16);
                }
            }
            int len = 16;
#pragma unroll
            for (int m = 8; m >= 1; m >>= 1) {
                int half = len >> 1;
                bool up = (lane & m) != 0;
#pragma unroll
                for (int k = 0; k < 8; k++) {
                    if (k < half) {
                        float send = up ? g16[k] : g16[k + half];
                        float keep = up ? g16[k + half] : g16[k];
                        g16[k] = keep + __shfl_xor_sync(FULL, send, m);
                    }
                }
                len = half;
            }
            logit += g16[0];
        }
    }

    float* ob = out + ((b * 32 + lane) * 8) * 4096 + hw;
#pragma unroll
    for (int o = 0; o < 8; o++)
        ob[o * 4096] = act[o];
}

// ---------------------------------------------------------------------------
extern "C" void kernel_launch(void* const* d_in, const int* in_sizes, int n_in,
                              void* d_out, int out_size) {
    const float* x = (const float*)d_in[0];
    const float* W = (const float*)d_in[1];
    const float* b = (const float*)d_in[2];
    float* out = (float*)d_out;

    cudaFuncSetAttribute(conv_mma_kernel,
                         cudaFuncAttributeMaxDynamicSharedMemorySize, SMEM_BYTES);

    prep_t_kernel<<<8192, 256>>>(x);
    prep_wA_kernel<<<400, 256>>>(W);
    conv_mma_kernel<<<dim3(32, 2, 32), 256, SMEM_BYTES>>>();
    routing_kernel<<<4096, 256>>>(b, out);
}